// round 14
// baseline (speedup 1.0000x reference)
#include <cuda_runtime.h>
#include <cuda_bf16.h>

#define T_STEPS 32768
#define IN_SIZE 1024
#define HID     64
#define GATES   256   // 4 * HID
#define CHUNK   16    // timesteps staged per cp.async.bulk (16KB)
#define NCHUNK  (T_STEPS / CHUNK)

// Scratch: precomputed input projection, (T, 4H) row-major. 33.5 MB static.
__device__ float g_xproj[T_STEPS * GATES];

// ---------------------------------------------------------------------------
// Math helpers
// ---------------------------------------------------------------------------
__device__ __forceinline__ float htanh(float x) {          // MUFU.TANH
    float r;
    asm("tanh.approx.f32 %0, %1;" : "=f"(r) : "f"(x));
    return r;
}
__device__ __forceinline__ void ffma2(unsigned long long& acc,
                                      unsigned long long a,
                                      unsigned long long b) {
    asm("fma.rn.f32x2 %0, %1, %2, %0;" : "+l"(acc) : "l"(a), "l"(b));
}
__device__ __forceinline__ unsigned long long fadd2(unsigned long long a,
                                                    unsigned long long b) {
    unsigned long long r;
    asm("add.rn.f32x2 %0, %1, %2;" : "=l"(r) : "l"(a), "l"(b));
    return r;
}
__device__ __forceinline__ float2 unpack2(unsigned long long v) {
    float2 r;
    asm("mov.b64 {%0, %1}, %2;" : "=f"(r.x), "=f"(r.y) : "l"(v));
    return r;
}
__device__ __forceinline__ unsigned smem_u32(const void* p) {
    return (unsigned)__cvta_generic_to_shared(p);
}

// ---------------------------------------------------------------------------
// Kernel 1: x_proj[t][j] = sum_k spec[k][t] * W_ih[j][k] + b_ih[j] + b_hh[j]
// Tiled FP32 GEMM: block = 64 timesteps x 256 gates, BK = 8, 256 threads,
// each thread computes an 8x8 (t x j) micro-tile.
// R14: register double-buffering of the global loads — next k-tile's LDGs
// issue right after the first barrier, hiding the ~600cyc latency under the
// ~550cyc compute phase. Accumulation order unchanged -> bit-identical.
// ---------------------------------------------------------------------------
__global__ void __launch_bounds__(256, 1)
gemm_xproj_kernel(const float* __restrict__ spec,
                  const float* __restrict__ W_ih,
                  const float* __restrict__ b_ih,
                  const float* __restrict__ b_hh)
{
    __shared__ float sS[8][64];    // [kk][t]
    __shared__ float sW[8][GATES]; // [kk][j]

    const int tid = threadIdx.x;
    const int t0  = blockIdx.x * 64;
    const int tj  = (tid & 31) * 8;  // j base (0..248)
    const int tt  = (tid >> 5) * 8;  // t base within tile (0..56)

    float acc[8][8];
#pragma unroll
    for (int i = 0; i < 8; i++)
#pragma unroll
        for (int j = 0; j < 8; j++) acc[i][j] = 0.f;

    const int krow = tid >> 6;   // 0..3
    const int tcol = tid & 63;   // 0..63

    // Preload k-tile 0 into registers
    float  pv0 = spec[(size_t)krow * T_STEPS + t0 + tcol];
    float  pv1 = spec[(size_t)(krow + 4) * T_STEPS + t0 + tcol];
    float4 pwa = *reinterpret_cast<const float4*>(W_ih + (size_t)tid * IN_SIZE);
    float4 pwb = *reinterpret_cast<const float4*>(W_ih + (size_t)tid * IN_SIZE + 4);

    for (int k0 = 0; k0 < IN_SIZE; k0 += 8) {
        // Store current k-tile (from registers) to smem
        sS[krow][tcol]     = pv0;
        sS[krow + 4][tcol] = pv1;
        sW[0][tid] = pwa.x; sW[1][tid] = pwa.y; sW[2][tid] = pwa.z; sW[3][tid] = pwa.w;
        sW[4][tid] = pwb.x; sW[5][tid] = pwb.y; sW[6][tid] = pwb.z; sW[7][tid] = pwb.w;
        __syncthreads();

        // Issue next k-tile's global loads NOW (latency hides under compute)
        if (k0 + 8 < IN_SIZE) {
            const int kn = k0 + 8;
            pv0 = spec[(size_t)(kn + krow) * T_STEPS + t0 + tcol];
            pv1 = spec[(size_t)(kn + krow + 4) * T_STEPS + t0 + tcol];
            pwa = *reinterpret_cast<const float4*>(W_ih + (size_t)tid * IN_SIZE + kn);
            pwb = *reinterpret_cast<const float4*>(W_ih + (size_t)tid * IN_SIZE + kn + 4);
        }

#pragma unroll
        for (int kk = 0; kk < 8; kk++) {
            float4 s0 = *reinterpret_cast<const float4*>(&sS[kk][tt]);
            float4 s1 = *reinterpret_cast<const float4*>(&sS[kk][tt + 4]);
            float4 w0 = *reinterpret_cast<const float4*>(&sW[kk][tj]);
            float4 w1 = *reinterpret_cast<const float4*>(&sW[kk][tj + 4]);
            float sv[8] = {s0.x, s0.y, s0.z, s0.w, s1.x, s1.y, s1.z, s1.w};
            float wv[8] = {w0.x, w0.y, w0.z, w0.w, w1.x, w1.y, w1.z, w1.w};
#pragma unroll
            for (int i = 0; i < 8; i++)
#pragma unroll
                for (int j = 0; j < 8; j++)
                    acc[i][j] = fmaf(sv[i], wv[j], acc[i][j]);
        }
        __syncthreads();
    }

    float bias[8];
#pragma unroll
    for (int j = 0; j < 8; j++) bias[j] = b_ih[tj + j] + b_hh[tj + j];

#pragma unroll
    for (int i = 0; i < 8; i++) {
        const int t = t0 + tt + i;
        float4 o0, o1;
        o0.x = acc[i][0] + bias[0]; o0.y = acc[i][1] + bias[1];
        o0.z = acc[i][2] + bias[2]; o0.w = acc[i][3] + bias[3];
        o1.x = acc[i][4] + bias[4]; o1.y = acc[i][5] + bias[5];
        o1.z = acc[i][6] + bias[6]; o1.w = acc[i][7] + bias[7];
        *reinterpret_cast<float4*>(&g_xproj[(size_t)t * GATES + tj])     = o0;
        *reinterpret_cast<float4*>(&g_xproj[(size_t)t * GATES + tj + 4]) = o1;
    }
}

// ---------------------------------------------------------------------------
// Kernel 2: sequential LSTM (UNCHANGED from R11 — best measured).
// Single block of 256 threads (8 warps, 2/SMSP). Thread = (u = tid>>2,
// gate = tid&3); full 64-weight row in registers (32 FFMA2); 4-lane shfl
// gate exchange; MUFU.TANH; double-buffered h; one __syncthreads per step.
// xproj staged into smem via double-buffered cp.async.bulk (16KB / 16 steps).
// ---------------------------------------------------------------------------
__global__ void __launch_bounds__(256, 1)
lstm_seq_kernel(const float* __restrict__ W_hh, float* __restrict__ out)
{
    __shared__ __align__(128) float s_x[2][CHUNK * GATES];   // 2 x 16KB
    __shared__ __align__(16)  float h_sh[2][HID];
    __shared__ __align__(8)   unsigned long long s_mbar[2];

    const int tid  = threadIdx.x;
    const int u    = tid >> 2;        // hidden unit 0..63
    const int gate = tid & 3;         // 0:i 1:f 2:g 3:o
    const int lane = tid & 31;
    const int lbase = lane & ~3;      // first lane of this unit's 4-lane group
    const int row  = gate * HID + u;  // W_hh / x_proj row for this thread

    // Load weight row as 32 packed f32 pairs (64 regs)
    unsigned long long wq[HID / 2];
    {
        const ulonglong2* wp =
            reinterpret_cast<const ulonglong2*>(W_hh + (size_t)row * HID);
#pragma unroll
        for (int i = 0; i < HID / 8; i++) {
            ulonglong2 v0 = wp[2 * i];
            ulonglong2 v1 = wp[2 * i + 1];
            wq[4 * i]     = v0.x; wq[4 * i + 1] = v0.y;
            wq[4 * i + 2] = v1.x; wq[4 * i + 3] = v1.y;
        }
    }

    // Activation folding: act = q * tanh(m * a) + r
    const float am = (gate == 2) ? 1.f : 0.5f;
    const float aq = am;
    const float ar = (gate == 2) ? 0.f : 0.5f;

    const unsigned mb0 = smem_u32(&s_mbar[0]);
    const unsigned mb1 = smem_u32(&s_mbar[1]);
    const unsigned bufaddr0 = smem_u32(&s_x[0][0]);
    const unsigned bufaddr1 = smem_u32(&s_x[1][0]);
    const unsigned CPBYTES = CHUNK * GATES * 4;   // 16384

    float c = 0.f;
    if (tid < HID) h_sh[0][tid] = 0.f;

    // Init mbarriers + issue the first two chunk loads (thread 0)
    if (tid == 0) {
        asm volatile("mbarrier.init.shared.b64 [%0], 1;" :: "r"(mb0) : "memory");
        asm volatile("mbarrier.init.shared.b64 [%0], 1;" :: "r"(mb1) : "memory");
        asm volatile("fence.proxy.async.shared::cta;" ::: "memory");
        asm volatile("mbarrier.arrive.expect_tx.shared.b64 _, [%0], %1;"
                     :: "r"(mb0), "r"(CPBYTES) : "memory");
        asm volatile("cp.async.bulk.shared::cta.global.mbarrier::complete_tx::bytes"
                     " [%0], [%1], %2, [%3];"
                     :: "r"(bufaddr0), "l"((const void*)&g_xproj[0]),
                        "r"(CPBYTES), "r"(mb0) : "memory");
        asm volatile("mbarrier.arrive.expect_tx.shared.b64 _, [%0], %1;"
                     :: "r"(mb1), "r"(CPBYTES) : "memory");
        asm volatile("cp.async.bulk.shared::cta.global.mbarrier::complete_tx::bytes"
                     " [%0], [%1], %2, [%3];"
                     :: "r"(bufaddr1), "l"((const void*)&g_xproj[CHUNK * GATES]),
                        "r"(CPBYTES), "r"(mb1) : "memory");
    }
    __syncthreads();

#define LSTM_STEP(XBASE, TT, RBUF)                                           \
    {                                                                        \
        const float xc = (XBASE)[(TT) * GATES + row];                        \
        unsigned long long a0 = 0ull, a1 = 0ull, a2 = 0ull, a3 = 0ull;       \
        const ulonglong2* hp =                                               \
            reinterpret_cast<const ulonglong2*>(&h_sh[(RBUF)][0]);           \
        _Pragma("unroll")                                                    \
        for (int k = 0; k < HID / 8; k++) {                                  \
            ulonglong2 hA = hp[2 * k];                                       \
            ulonglong2 hB = hp[2 * k + 1];                                   \
            ffma2(a0, hA.x, wq[4 * k]);                                      \
            ffma2(a1, hA.y, wq[4 * k + 1]);                                  \
            ffma2(a2, hB.x, wq[4 * k + 2]);                                  \
            ffma2(a3, hB.y, wq[4 * k + 3]);                                  \
        }                                                                    \
        float2 fs = unpack2(fadd2(fadd2(a0, a1), fadd2(a2, a3)));            \
        const float a = xc + (fs.x + fs.y);                                  \
        const float act = fmaf(aq, htanh(am * a), ar);                       \
        const float i_a = __shfl_sync(0xffffffffu, act, lbase + 0);          \
        const float f_a = __shfl_sync(0xffffffffu, act, lbase + 1);          \
        const float g_a = __shfl_sync(0xffffffffu, act, lbase + 2);          \
        const float o_a = __shfl_sync(0xffffffffu, act, lbase + 3);          \
        c = fmaf(f_a, c, i_a * g_a);                                         \
        const float th = htanh(c);                                           \
        if (gate == 0) h_sh[(RBUF) ^ 1][u] = o_a * th;                       \
        __syncthreads();                                                     \
    }

    for (int ch = 0; ch < NCHUNK; ch++) {
        const int b = ch & 1;
        const unsigned mb = b ? mb1 : mb0;
        const unsigned ph = (unsigned)((ch >> 1) & 1);
        const float* xb = &s_x[b][0];

        // Wait for this chunk's data (fast-path try_wait when complete)
        {
            unsigned done;
            asm volatile(
                "{\n\t.reg .pred p;\n\t"
                "mbarrier.try_wait.parity.acquire.cta.shared::cta.b64 p, [%1], %2;\n\t"
                "selp.b32 %0, 1, 0, p;\n\t}"
                : "=r"(done) : "r"(mb), "r"(ph) : "memory");
            while (!done) {
                asm volatile(
                    "{\n\t.reg .pred p;\n\t"
                    "mbarrier.try_wait.parity.acquire.cta.shared::cta.b64 p, [%1], %2, 0x989680;\n\t"
                    "selp.b32 %0, 1, 0, p;\n\t}"
                    : "=r"(done) : "r"(mb), "r"(ph) : "memory");
            }
        }

        LSTM_STEP(xb, 0,  0);  LSTM_STEP(xb, 1,  1);
        LSTM_STEP(xb, 2,  0);  LSTM_STEP(xb, 3,  1);
        LSTM_STEP(xb, 4,  0);  LSTM_STEP(xb, 5,  1);
        LSTM_STEP(xb, 6,  0);  LSTM_STEP(xb, 7,  1);
        LSTM_STEP(xb, 8,  0);  LSTM_STEP(xb, 9,  1);
        LSTM_STEP(xb, 10, 0);  LSTM_STEP(xb, 11, 1);
        LSTM_STEP(xb, 12, 0);  LSTM_STEP(xb, 13, 1);
        LSTM_STEP(xb, 14, 0);  LSTM_STEP(xb, 15, 1);

        // Refill this buffer with chunk ch+2 (safe: all reads completed)
        if (tid == 0 && ch + 2 < NCHUNK) {
            const unsigned dst = b ? bufaddr1 : bufaddr0;
            asm volatile("mbarrier.arrive.expect_tx.shared.b64 _, [%0], %1;"
                         :: "r"(mb), "r"(CPBYTES) : "memory");
            asm volatile("cp.async.bulk.shared::cta.global.mbarrier::complete_tx::bytes"
                         " [%0], [%1], %2, [%3];"
                         :: "r"(dst),
                            "l"((const void*)&g_xproj[(size_t)(ch + 2) * CHUNK * GATES]),
                            "r"(CPBYTES), "r"(mb) : "memory");
        }
    }
#undef LSTM_STEP

    // log_softmax over final h (accurate libm; runs once). Final h in buf 0.
    if (tid < HID) {
        const float* hf = h_sh[T_STEPS & 1];
        float m = -1e30f;
#pragma unroll 8
        for (int k = 0; k < HID; k++) m = fmaxf(m, hf[k]);
        float sum = 0.f;
#pragma unroll 8
        for (int k = 0; k < HID; k++) sum += expf(hf[k] - m);
        out[tid] = hf[tid] - m - logf(sum);
    }
}

// ---------------------------------------------------------------------------
// Launch: inputs in metadata order: spectrogram, W_ih, W_hh, b_ih, b_hh
// ---------------------------------------------------------------------------
extern "C" void kernel_launch(void* const* d_in, const int* in_sizes, int n_in,
                              void* d_out, int out_size)
{
    const float* spec = (const float*)d_in[0];
    const float* W_ih = (const float*)d_in[1];
    const float* W_hh = (const float*)d_in[2];
    const float* b_ih = (const float*)d_in[3];
    const float* b_hh = (const float*)d_in[4];
    float* out = (float*)d_out;

    gemm_xproj_kernel<<<T_STEPS / 64, 256>>>(spec, W_ih, b_ih, b_hh);
    lstm_seq_kernel<<<1, 256>>>(W_hh, out);
}

// round 15
// speedup vs baseline: 1.6266x; 1.6266x over previous
#include <cuda_runtime.h>
#include <cuda_bf16.h>

#define T_STEPS 32768
#define IN_SIZE 1024
#define HID     64
#define GATES   256   // 4 * HID
#define CHUNK   16    // timesteps staged per cp.async.bulk (16KB)
#define NCHUNK  (T_STEPS / CHUNK)

// Scratch: precomputed input projection, (T, 4H) row-major. 33.5 MB static.
__device__ float g_xproj[T_STEPS * GATES];

// ---------------------------------------------------------------------------
// Math helpers
// ---------------------------------------------------------------------------
__device__ __forceinline__ float htanh(float x) {          // MUFU.TANH
    float r;
    asm("tanh.approx.f32 %0, %1;" : "=f"(r) : "f"(x));
    return r;
}
__device__ __forceinline__ void ffma2(unsigned long long& acc,
                                      unsigned long long a,
                                      unsigned long long b) {
    asm("fma.rn.f32x2 %0, %1, %2, %0;" : "+l"(acc) : "l"(a), "l"(b));
}
__device__ __forceinline__ unsigned long long fadd2(unsigned long long a,
                                                    unsigned long long b) {
    unsigned long long r;
    asm("add.rn.f32x2 %0, %1, %2;" : "=l"(r) : "l"(a), "l"(b));
    return r;
}
__device__ __forceinline__ float2 unpack2(unsigned long long v) {
    float2 r;
    asm("mov.b64 {%0, %1}, %2;" : "=f"(r.x), "=f"(r.y) : "l"(v));
    return r;
}
__device__ __forceinline__ unsigned smem_u32(const void* p) {
    return (unsigned)__cvta_generic_to_shared(p);
}

// ---------------------------------------------------------------------------
// Kernel 1: x_proj[t][j] = sum_k spec[k][t] * W_ih[j][k] + b_ih[j] + b_hh[j]
// Tiled FP32 GEMM: block = 64 timesteps x 256 gates, BK = 8, 256 threads,
// each thread computes an 8x8 (t x j) micro-tile. (Exact R11 version.)
// ---------------------------------------------------------------------------
__global__ void __launch_bounds__(256, 1)
gemm_xproj_kernel(const float* __restrict__ spec,
                  const float* __restrict__ W_ih,
                  const float* __restrict__ b_ih,
                  const float* __restrict__ b_hh)
{
    __shared__ float sS[8][64];    // [kk][t]
    __shared__ float sW[8][GATES]; // [kk][j]

    const int tid = threadIdx.x;
    const int t0  = blockIdx.x * 64;
    const int tj  = (tid & 31) * 8;  // j base (0..248)
    const int tt  = (tid >> 5) * 8;  // t base within tile (0..56)

    float acc[8][8];
#pragma unroll
    for (int i = 0; i < 8; i++)
#pragma unroll
        for (int j = 0; j < 8; j++) acc[i][j] = 0.f;

    const int krow = tid >> 6;   // 0..3
    const int tcol = tid & 63;   // 0..63

    for (int k0 = 0; k0 < IN_SIZE; k0 += 8) {
        sS[krow][tcol]     = spec[(size_t)(k0 + krow) * T_STEPS + t0 + tcol];
        sS[krow + 4][tcol] = spec[(size_t)(k0 + krow + 4) * T_STEPS + t0 + tcol];
        float4 wa = *reinterpret_cast<const float4*>(W_ih + (size_t)tid * IN_SIZE + k0);
        float4 wb = *reinterpret_cast<const float4*>(W_ih + (size_t)tid * IN_SIZE + k0 + 4);
        sW[0][tid] = wa.x; sW[1][tid] = wa.y; sW[2][tid] = wa.z; sW[3][tid] = wa.w;
        sW[4][tid] = wb.x; sW[5][tid] = wb.y; sW[6][tid] = wb.z; sW[7][tid] = wb.w;
        __syncthreads();

#pragma unroll
        for (int kk = 0; kk < 8; kk++) {
            float4 s0 = *reinterpret_cast<const float4*>(&sS[kk][tt]);
            float4 s1 = *reinterpret_cast<const float4*>(&sS[kk][tt + 4]);
            float4 w0 = *reinterpret_cast<const float4*>(&sW[kk][tj]);
            float4 w1 = *reinterpret_cast<const float4*>(&sW[kk][tj + 4]);
            float sv[8] = {s0.x, s0.y, s0.z, s0.w, s1.x, s1.y, s1.z, s1.w};
            float wv[8] = {w0.x, w0.y, w0.z, w0.w, w1.x, w1.y, w1.z, w1.w};
#pragma unroll
            for (int i = 0; i < 8; i++)
#pragma unroll
                for (int j = 0; j < 8; j++)
                    acc[i][j] = fmaf(sv[i], wv[j], acc[i][j]);
        }
        __syncthreads();
    }

    float bias[8];
#pragma unroll
    for (int j = 0; j < 8; j++) bias[j] = b_ih[tj + j] + b_hh[tj + j];

#pragma unroll
    for (int i = 0; i < 8; i++) {
        const int t = t0 + tt + i;
        float4 o0, o1;
        o0.x = acc[i][0] + bias[0]; o0.y = acc[i][1] + bias[1];
        o0.z = acc[i][2] + bias[2]; o0.w = acc[i][3] + bias[3];
        o1.x = acc[i][4] + bias[4]; o1.y = acc[i][5] + bias[5];
        o1.z = acc[i][6] + bias[6]; o1.w = acc[i][7] + bias[7];
        *reinterpret_cast<float4*>(&g_xproj[(size_t)t * GATES + tj])     = o0;
        *reinterpret_cast<float4*>(&g_xproj[(size_t)t * GATES + tj + 4]) = o1;
    }
}

// ---------------------------------------------------------------------------
// Kernel 2: sequential LSTM (exact R11 version — best measured).
// Single block of 256 threads (8 warps, 2/SMSP). Thread = (u = tid>>2,
// gate = tid&3); full 64-weight row in registers (32 FFMA2); 4-lane shfl
// gate exchange; MUFU.TANH; double-buffered h; one __syncthreads per step.
// xproj staged into smem via double-buffered cp.async.bulk (16KB / 16 steps).
// ---------------------------------------------------------------------------
__global__ void __launch_bounds__(256, 1)
lstm_seq_kernel(const float* __restrict__ W_hh, float* __restrict__ out)
{
    __shared__ __align__(128) float s_x[2][CHUNK * GATES];   // 2 x 16KB
    __shared__ __align__(16)  float h_sh[2][HID];
    __shared__ __align__(8)   unsigned long long s_mbar[2];

    const int tid  = threadIdx.x;
    const int u    = tid >> 2;        // hidden unit 0..63
    const int gate = tid & 3;         // 0:i 1:f 2:g 3:o
    const int lane = tid & 31;
    const int lbase = lane & ~3;      // first lane of this unit's 4-lane group
    const int row  = gate * HID + u;  // W_hh / x_proj row for this thread

    // Load weight row as 32 packed f32 pairs (64 regs)
    unsigned long long wq[HID / 2];
    {
        const ulonglong2* wp =
            reinterpret_cast<const ulonglong2*>(W_hh + (size_t)row * HID);
#pragma unroll
        for (int i = 0; i < HID / 8; i++) {
            ulonglong2 v0 = wp[2 * i];
            ulonglong2 v1 = wp[2 * i + 1];
            wq[4 * i]     = v0.x; wq[4 * i + 1] = v0.y;
            wq[4 * i + 2] = v1.x; wq[4 * i + 3] = v1.y;
        }
    }

    // Activation folding: act = q * tanh(m * a) + r
    const float am = (gate == 2) ? 1.f : 0.5f;
    const float aq = am;
    const float ar = (gate == 2) ? 0.f : 0.5f;

    const unsigned mb0 = smem_u32(&s_mbar[0]);
    const unsigned mb1 = smem_u32(&s_mbar[1]);
    const unsigned bufaddr0 = smem_u32(&s_x[0][0]);
    const unsigned bufaddr1 = smem_u32(&s_x[1][0]);
    const unsigned CPBYTES = CHUNK * GATES * 4;   // 16384

    float c = 0.f;
    if (tid < HID) h_sh[0][tid] = 0.f;

    // Init mbarriers + issue the first two chunk loads (thread 0)
    if (tid == 0) {
        asm volatile("mbarrier.init.shared.b64 [%0], 1;" :: "r"(mb0) : "memory");
        asm volatile("mbarrier.init.shared.b64 [%0], 1;" :: "r"(mb1) : "memory");
        asm volatile("fence.proxy.async.shared::cta;" ::: "memory");
        asm volatile("mbarrier.arrive.expect_tx.shared.b64 _, [%0], %1;"
                     :: "r"(mb0), "r"(CPBYTES) : "memory");
        asm volatile("cp.async.bulk.shared::cta.global.mbarrier::complete_tx::bytes"
                     " [%0], [%1], %2, [%3];"
                     :: "r"(bufaddr0), "l"((const void*)&g_xproj[0]),
                        "r"(CPBYTES), "r"(mb0) : "memory");
        asm volatile("mbarrier.arrive.expect_tx.shared.b64 _, [%0], %1;"
                     :: "r"(mb1), "r"(CPBYTES) : "memory");
        asm volatile("cp.async.bulk.shared::cta.global.mbarrier::complete_tx::bytes"
                     " [%0], [%1], %2, [%3];"
                     :: "r"(bufaddr1), "l"((const void*)&g_xproj[CHUNK * GATES]),
                        "r"(CPBYTES), "r"(mb1) : "memory");
    }
    __syncthreads();

#define LSTM_STEP(XBASE, TT, RBUF)                                           \
    {                                                                        \
        const float xc = (XBASE)[(TT) * GATES + row];                        \
        unsigned long long a0 = 0ull, a1 = 0ull, a2 = 0ull, a3 = 0ull;       \
        const ulonglong2* hp =                                               \
            reinterpret_cast<const ulonglong2*>(&h_sh[(RBUF)][0]);           \
        _Pragma("unroll")                                                    \
        for (int k = 0; k < HID / 8; k++) {                                  \
            ulonglong2 hA = hp[2 * k];                                       \
            ulonglong2 hB = hp[2 * k + 1];                                   \
            ffma2(a0, hA.x, wq[4 * k]);                                      \
            ffma2(a1, hA.y, wq[4 * k + 1]);                                  \
            ffma2(a2, hB.x, wq[4 * k + 2]);                                  \
            ffma2(a3, hB.y, wq[4 * k + 3]);                                  \
        }                                                                    \
        float2 fs = unpack2(fadd2(fadd2(a0, a1), fadd2(a2, a3)));            \
        const float a = xc + (fs.x + fs.y);                                  \
        const float act = fmaf(aq, htanh(am * a), ar);                       \
        const float i_a = __shfl_sync(0xffffffffu, act, lbase + 0);          \
        const float f_a = __shfl_sync(0xffffffffu, act, lbase + 1);          \
        const float g_a = __shfl_sync(0xffffffffu, act, lbase + 2);          \
        const float o_a = __shfl_sync(0xffffffffu, act, lbase + 3);          \
        c = fmaf(f_a, c, i_a * g_a);                                         \
        const float th = htanh(c);                                           \
        if (gate == 0) h_sh[(RBUF) ^ 1][u] = o_a * th;                       \
        __syncthreads();                                                     \
    }

    for (int ch = 0; ch < NCHUNK; ch++) {
        const int b = ch & 1;
        const unsigned mb = b ? mb1 : mb0;
        const unsigned ph = (unsigned)((ch >> 1) & 1);
        const float* xb = &s_x[b][0];

        // Wait for this chunk's data (fast-path try_wait when complete)
        {
            unsigned done;
            asm volatile(
                "{\n\t.reg .pred p;\n\t"
                "mbarrier.try_wait.parity.acquire.cta.shared::cta.b64 p, [%1], %2;\n\t"
                "selp.b32 %0, 1, 0, p;\n\t}"
                : "=r"(done) : "r"(mb), "r"(ph) : "memory");
            while (!done) {
                asm volatile(
                    "{\n\t.reg .pred p;\n\t"
                    "mbarrier.try_wait.parity.acquire.cta.shared::cta.b64 p, [%1], %2, 0x989680;\n\t"
                    "selp.b32 %0, 1, 0, p;\n\t}"
                    : "=r"(done) : "r"(mb), "r"(ph) : "memory");
            }
        }

        LSTM_STEP(xb, 0,  0);  LSTM_STEP(xb, 1,  1);
        LSTM_STEP(xb, 2,  0);  LSTM_STEP(xb, 3,  1);
        LSTM_STEP(xb, 4,  0);  LSTM_STEP(xb, 5,  1);
        LSTM_STEP(xb, 6,  0);  LSTM_STEP(xb, 7,  1);
        LSTM_STEP(xb, 8,  0);  LSTM_STEP(xb, 9,  1);
        LSTM_STEP(xb, 10, 0);  LSTM_STEP(xb, 11, 1);
        LSTM_STEP(xb, 12, 0);  LSTM_STEP(xb, 13, 1);
        LSTM_STEP(xb, 14, 0);  LSTM_STEP(xb, 15, 1);

        // Refill this buffer with chunk ch+2 (safe: all reads completed)
        if (tid == 0 && ch + 2 < NCHUNK) {
            const unsigned dst = b ? bufaddr1 : bufaddr0;
            asm volatile("mbarrier.arrive.expect_tx.shared.b64 _, [%0], %1;"
                         :: "r"(mb), "r"(CPBYTES) : "memory");
            asm volatile("cp.async.bulk.shared::cta.global.mbarrier::complete_tx::bytes"
                         " [%0], [%1], %2, [%3];"
                         :: "r"(dst),
                            "l"((const void*)&g_xproj[(size_t)(ch + 2) * CHUNK * GATES]),
                            "r"(CPBYTES), "r"(mb) : "memory");
        }
    }
#undef LSTM_STEP

    // log_softmax over final h (accurate libm; runs once). Final h in buf 0.
    if (tid < HID) {
        const float* hf = h_sh[T_STEPS & 1];
        float m = -1e30f;
#pragma unroll 8
        for (int k = 0; k < HID; k++) m = fmaxf(m, hf[k]);
        float sum = 0.f;
#pragma unroll 8
        for (int k = 0; k < HID; k++) sum += expf(hf[k] - m);
        out[tid] = hf[tid] - m - logf(sum);
    }
}

// ---------------------------------------------------------------------------
// Launch: inputs in metadata order: spectrogram, W_ih, W_hh, b_ih, b_hh
// ---------------------------------------------------------------------------
extern "C" void kernel_launch(void* const* d_in, const int* in_sizes, int n_in,
                              void* d_out, int out_size)
{
    const float* spec = (const float*)d_in[0];
    const float* W_ih = (const float*)d_in[1];
    const float* W_hh = (const float*)d_in[2];
    const float* b_ih = (const float*)d_in[3];
    const float* b_hh = (const float*)d_in[4];
    float* out = (float*)d_out;

    gemm_xproj_kernel<<<T_STEPS / 64, 256>>>(spec, W_ih, b_ih, b_hh);
    lstm_seq_kernel<<<1, 256>>>(W_hh, out);
}

// round 16
// speedup vs baseline: 1.6454x; 1.0116x over previous
#include <cuda_runtime.h>
#include <cuda_bf16.h>

#define T_STEPS 32768
#define IN_SIZE 1024
#define HID     64
#define GATES   256   // 4 * HID
#define CHUNK   16    // timesteps staged per cp.async.bulk (16KB)
#define NCHUNK  (T_STEPS / CHUNK)

// Scratch: precomputed input projection, (T, 4H) row-major. 33.5 MB static.
__device__ float g_xproj[T_STEPS * GATES];

// ---------------------------------------------------------------------------
// Math helpers
// ---------------------------------------------------------------------------
__device__ __forceinline__ float htanh(float x) {          // MUFU.TANH
    float r;
    asm("tanh.approx.f32 %0, %1;" : "=f"(r) : "f"(x));
    return r;
}
__device__ __forceinline__ void ffma2(unsigned long long& acc,
                                      unsigned long long a,
                                      unsigned long long b) {
    asm("fma.rn.f32x2 %0, %1, %2, %0;" : "+l"(acc) : "l"(a), "l"(b));
}
__device__ __forceinline__ unsigned long long fadd2(unsigned long long a,
                                                    unsigned long long b) {
    unsigned long long r;
    asm("add.rn.f32x2 %0, %1, %2;" : "=l"(r) : "l"(a), "l"(b));
    return r;
}
__device__ __forceinline__ float2 unpack2(unsigned long long v) {
    float2 r;
    asm("mov.b64 {%0, %1}, %2;" : "=f"(r.x), "=f"(r.y) : "l"(v));
    return r;
}
__device__ __forceinline__ unsigned smem_u32(const void* p) {
    return (unsigned)__cvta_generic_to_shared(p);
}

// ---------------------------------------------------------------------------
// Kernel 1: x_proj[t][j] = sum_k spec[k][t] * W_ih[j][k] + b_ih[j] + b_hh[j]
// Tiled FP32 GEMM: block = 64 timesteps x 256 gates, BK = 8, 256 threads,
// each thread computes an 8x8 (t x j) micro-tile.
// R16 (= R14 retried at healthy clocks): register double-buffering of the
// global loads — next k-tile's LDGs issue right after the first barrier,
// hiding the ~600cyc latency under the ~550cyc compute phase.
// Accumulation order unchanged -> bit-identical output.
// ---------------------------------------------------------------------------
__global__ void __launch_bounds__(256, 1)
gemm_xproj_kernel(const float* __restrict__ spec,
                  const float* __restrict__ W_ih,
                  const float* __restrict__ b_ih,
                  const float* __restrict__ b_hh)
{
    __shared__ float sS[8][64];    // [kk][t]
    __shared__ float sW[8][GATES]; // [kk][j]

    const int tid = threadIdx.x;
    const int t0  = blockIdx.x * 64;
    const int tj  = (tid & 31) * 8;  // j base (0..248)
    const int tt  = (tid >> 5) * 8;  // t base within tile (0..56)

    float acc[8][8];
#pragma unroll
    for (int i = 0; i < 8; i++)
#pragma unroll
        for (int j = 0; j < 8; j++) acc[i][j] = 0.f;

    const int krow = tid >> 6;   // 0..3
    const int tcol = tid & 63;   // 0..63

    // Preload k-tile 0 into registers
    float  pv0 = spec[(size_t)krow * T_STEPS + t0 + tcol];
    float  pv1 = spec[(size_t)(krow + 4) * T_STEPS + t0 + tcol];
    float4 pwa = *reinterpret_cast<const float4*>(W_ih + (size_t)tid * IN_SIZE);
    float4 pwb = *reinterpret_cast<const float4*>(W_ih + (size_t)tid * IN_SIZE + 4);

    for (int k0 = 0; k0 < IN_SIZE; k0 += 8) {
        // Store current k-tile (from registers) to smem
        sS[krow][tcol]     = pv0;
        sS[krow + 4][tcol] = pv1;
        sW[0][tid] = pwa.x; sW[1][tid] = pwa.y; sW[2][tid] = pwa.z; sW[3][tid] = pwa.w;
        sW[4][tid] = pwb.x; sW[5][tid] = pwb.y; sW[6][tid] = pwb.z; sW[7][tid] = pwb.w;
        __syncthreads();

        // Issue next k-tile's global loads NOW (latency hides under compute)
        if (k0 + 8 < IN_SIZE) {
            const int kn = k0 + 8;
            pv0 = spec[(size_t)(kn + krow) * T_STEPS + t0 + tcol];
            pv1 = spec[(size_t)(kn + krow + 4) * T_STEPS + t0 + tcol];
            pwa = *reinterpret_cast<const float4*>(W_ih + (size_t)tid * IN_SIZE + kn);
            pwb = *reinterpret_cast<const float4*>(W_ih + (size_t)tid * IN_SIZE + kn + 4);
        }

#pragma unroll
        for (int kk = 0; kk < 8; kk++) {
            float4 s0 = *reinterpret_cast<const float4*>(&sS[kk][tt]);
            float4 s1 = *reinterpret_cast<const float4*>(&sS[kk][tt + 4]);
            float4 w0 = *reinterpret_cast<const float4*>(&sW[kk][tj]);
            float4 w1 = *reinterpret_cast<const float4*>(&sW[kk][tj + 4]);
            float sv[8] = {s0.x, s0.y, s0.z, s0.w, s1.x, s1.y, s1.z, s1.w};
            float wv[8] = {w0.x, w0.y, w0.z, w0.w, w1.x, w1.y, w1.z, w1.w};
#pragma unroll
            for (int i = 0; i < 8; i++)
#pragma unroll
                for (int j = 0; j < 8; j++)
                    acc[i][j] = fmaf(sv[i], wv[j], acc[i][j]);
        }
        __syncthreads();
    }

    float bias[8];
#pragma unroll
    for (int j = 0; j < 8; j++) bias[j] = b_ih[tj + j] + b_hh[tj + j];

#pragma unroll
    for (int i = 0; i < 8; i++) {
        const int t = t0 + tt + i;
        float4 o0, o1;
        o0.x = acc[i][0] + bias[0]; o0.y = acc[i][1] + bias[1];
        o0.z = acc[i][2] + bias[2]; o0.w = acc[i][3] + bias[3];
        o1.x = acc[i][4] + bias[4]; o1.y = acc[i][5] + bias[5];
        o1.z = acc[i][6] + bias[6]; o1.w = acc[i][7] + bias[7];
        *reinterpret_cast<float4*>(&g_xproj[(size_t)t * GATES + tj])     = o0;
        *reinterpret_cast<float4*>(&g_xproj[(size_t)t * GATES + tj + 4]) = o1;
    }
}

// ---------------------------------------------------------------------------
// Kernel 2: sequential LSTM (exact R11 version — best measured, FROZEN).
// Single block of 256 threads (8 warps, 2/SMSP). Thread = (u = tid>>2,
// gate = tid&3); full 64-weight row in registers (32 FFMA2); 4-lane shfl
// gate exchange; MUFU.TANH; double-buffered h; one __syncthreads per step.
// xproj staged into smem via double-buffered cp.async.bulk (16KB / 16 steps).
// ---------------------------------------------------------------------------
__global__ void __launch_bounds__(256, 1)
lstm_seq_kernel(const float* __restrict__ W_hh, float* __restrict__ out)
{
    __shared__ __align__(128) float s_x[2][CHUNK * GATES];   // 2 x 16KB
    __shared__ __align__(16)  float h_sh[2][HID];
    __shared__ __align__(8)   unsigned long long s_mbar[2];

    const int tid  = threadIdx.x;
    const int u    = tid >> 2;        // hidden unit 0..63
    const int gate = tid & 3;         // 0:i 1:f 2:g 3:o
    const int lane = tid & 31;
    const int lbase = lane & ~3;      // first lane of this unit's 4-lane group
    const int row  = gate * HID + u;  // W_hh / x_proj row for this thread

    // Load weight row as 32 packed f32 pairs (64 regs)
    unsigned long long wq[HID / 2];
    {
        const ulonglong2* wp =
            reinterpret_cast<const ulonglong2*>(W_hh + (size_t)row * HID);
#pragma unroll
        for (int i = 0; i < HID / 8; i++) {
            ulonglong2 v0 = wp[2 * i];
            ulonglong2 v1 = wp[2 * i + 1];
            wq[4 * i]     = v0.x; wq[4 * i + 1] = v0.y;
            wq[4 * i + 2] = v1.x; wq[4 * i + 3] = v1.y;
        }
    }

    // Activation folding: act = q * tanh(m * a) + r
    const float am = (gate == 2) ? 1.f : 0.5f;
    const float aq = am;
    const float ar = (gate == 2) ? 0.f : 0.5f;

    const unsigned mb0 = smem_u32(&s_mbar[0]);
    const unsigned mb1 = smem_u32(&s_mbar[1]);
    const unsigned bufaddr0 = smem_u32(&s_x[0][0]);
    const unsigned bufaddr1 = smem_u32(&s_x[1][0]);
    const unsigned CPBYTES = CHUNK * GATES * 4;   // 16384

    float c = 0.f;
    if (tid < HID) h_sh[0][tid] = 0.f;

    // Init mbarriers + issue the first two chunk loads (thread 0)
    if (tid == 0) {
        asm volatile("mbarrier.init.shared.b64 [%0], 1;" :: "r"(mb0) : "memory");
        asm volatile("mbarrier.init.shared.b64 [%0], 1;" :: "r"(mb1) : "memory");
        asm volatile("fence.proxy.async.shared::cta;" ::: "memory");
        asm volatile("mbarrier.arrive.expect_tx.shared.b64 _, [%0], %1;"
                     :: "r"(mb0), "r"(CPBYTES) : "memory");
        asm volatile("cp.async.bulk.shared::cta.global.mbarrier::complete_tx::bytes"
                     " [%0], [%1], %2, [%3];"
                     :: "r"(bufaddr0), "l"((const void*)&g_xproj[0]),
                        "r"(CPBYTES), "r"(mb0) : "memory");
        asm volatile("mbarrier.arrive.expect_tx.shared.b64 _, [%0], %1;"
                     :: "r"(mb1), "r"(CPBYTES) : "memory");
        asm volatile("cp.async.bulk.shared::cta.global.mbarrier::complete_tx::bytes"
                     " [%0], [%1], %2, [%3];"
                     :: "r"(bufaddr1), "l"((const void*)&g_xproj[CHUNK * GATES]),
                        "r"(CPBYTES), "r"(mb1) : "memory");
    }
    __syncthreads();

#define LSTM_STEP(XBASE, TT, RBUF)                                           \
    {                                                                        \
        const float xc = (XBASE)[(TT) * GATES + row];                        \
        unsigned long long a0 = 0ull, a1 = 0ull, a2 = 0ull, a3 = 0ull;       \
        const ulonglong2* hp =                                               \
            reinterpret_cast<const ulonglong2*>(&h_sh[(RBUF)][0]);           \
        _Pragma("unroll")                                                    \
        for (int k = 0; k < HID / 8; k++) {                                  \
            ulonglong2 hA = hp[2 * k];                                       \
            ulonglong2 hB = hp[2 * k + 1];                                   \
            ffma2(a0, hA.x, wq[4 * k]);                                      \
            ffma2(a1, hA.y, wq[4 * k + 1]);                                  \
            ffma2(a2, hB.x, wq[4 * k + 2]);                                  \
            ffma2(a3, hB.y, wq[4 * k + 3]);                                  \
        }                                                                    \
        float2 fs = unpack2(fadd2(fadd2(a0, a1), fadd2(a2, a3)));            \
        const float a = xc + (fs.x + fs.y);                                  \
        const float act = fmaf(aq, htanh(am * a), ar);                       \
        const float i_a = __shfl_sync(0xffffffffu, act, lbase + 0);          \
        const float f_a = __shfl_sync(0xffffffffu, act, lbase + 1);          \
        const float g_a = __shfl_sync(0xffffffffu, act, lbase + 2);          \
        const float o_a = __shfl_sync(0xffffffffu, act, lbase + 3);          \
        c = fmaf(f_a, c, i_a * g_a);                                         \
        const float th = htanh(c);                                           \
        if (gate == 0) h_sh[(RBUF) ^ 1][u] = o_a * th;                       \
        __syncthreads();                                                     \
    }

    for (int ch = 0; ch < NCHUNK; ch++) {
        const int b = ch & 1;
        const unsigned mb = b ? mb1 : mb0;
        const unsigned ph = (unsigned)((ch >> 1) & 1);
        const float* xb = &s_x[b][0];

        // Wait for this chunk's data (fast-path try_wait when complete)
        {
            unsigned done;
            asm volatile(
                "{\n\t.reg .pred p;\n\t"
                "mbarrier.try_wait.parity.acquire.cta.shared::cta.b64 p, [%1], %2;\n\t"
                "selp.b32 %0, 1, 0, p;\n\t}"
                : "=r"(done) : "r"(mb), "r"(ph) : "memory");
            while (!done) {
                asm volatile(
                    "{\n\t.reg .pred p;\n\t"
                    "mbarrier.try_wait.parity.acquire.cta.shared::cta.b64 p, [%1], %2, 0x989680;\n\t"
                    "selp.b32 %0, 1, 0, p;\n\t}"
                    : "=r"(done) : "r"(mb), "r"(ph) : "memory");
            }
        }

        LSTM_STEP(xb, 0,  0);  LSTM_STEP(xb, 1,  1);
        LSTM_STEP(xb, 2,  0);  LSTM_STEP(xb, 3,  1);
        LSTM_STEP(xb, 4,  0);  LSTM_STEP(xb, 5,  1);
        LSTM_STEP(xb, 6,  0);  LSTM_STEP(xb, 7,  1);
        LSTM_STEP(xb, 8,  0);  LSTM_STEP(xb, 9,  1);
        LSTM_STEP(xb, 10, 0);  LSTM_STEP(xb, 11, 1);
        LSTM_STEP(xb, 12, 0);  LSTM_STEP(xb, 13, 1);
        LSTM_STEP(xb, 14, 0);  LSTM_STEP(xb, 15, 1);

        // Refill this buffer with chunk ch+2 (safe: all reads completed)
        if (tid == 0 && ch + 2 < NCHUNK) {
            const unsigned dst = b ? bufaddr1 : bufaddr0;
            asm volatile("mbarrier.arrive.expect_tx.shared.b64 _, [%0], %1;"
                         :: "r"(mb), "r"(CPBYTES) : "memory");
            asm volatile("cp.async.bulk.shared::cta.global.mbarrier::complete_tx::bytes"
                         " [%0], [%1], %2, [%3];"
                         :: "r"(dst),
                            "l"((const void*)&g_xproj[(size_t)(ch + 2) * CHUNK * GATES]),
                            "r"(CPBYTES), "r"(mb) : "memory");
        }
    }
#undef LSTM_STEP

    // log_softmax over final h (accurate libm; runs once). Final h in buf 0.
    if (tid < HID) {
        const float* hf = h_sh[T_STEPS & 1];
        float m = -1e30f;
#pragma unroll 8
        for (int k = 0; k < HID; k++) m = fmaxf(m, hf[k]);
        float sum = 0.f;
#pragma unroll 8
        for (int k = 0; k < HID; k++) sum += expf(hf[k] - m);
        out[tid] = hf[tid] - m - logf(sum);
    }
}

// ---------------------------------------------------------------------------
// Launch: inputs in metadata order: spectrogram, W_ih, W_hh, b_ih, b_hh
// ---------------------------------------------------------------------------
extern "C" void kernel_launch(void* const* d_in, const int* in_sizes, int n_in,
                              void* d_out, int out_size)
{
    const float* spec = (const float*)d_in[0];
    const float* W_ih = (const float*)d_in[1];
    const float* W_hh = (const float*)d_in[2];
    const float* b_ih = (const float*)d_in[3];
    const float* b_hh = (const float*)d_in[4];
    float* out = (float*)d_out;

    gemm_xproj_kernel<<<T_STEPS / 64, 256>>>(spec, W_ih, b_ih, b_hh);
    lstm_seq_kernel<<<1, 256>>>(W_hh, out);
}